// round 12
// baseline (speedup 1.0000x reference)
#include <cuda_runtime.h>

#define BB 256
#define NN 512
#define INF 10
#define HIDF 32
#define R 16                      // rows per block
#define WARPS 8
#define THREADS (WARPS * 32)
#define CHUNKS (NN / R)           // 32
#define TP 520                    // transposed s row length (512 + 8 pad)

typedef unsigned long long u64;

// ---- packed f32x2 helpers (sm_103a FFMA2 path, PTX-only) -------------------
__device__ __forceinline__ u64 pk2(float lo, float hi) {
    u64 r; asm("mov.b64 %0,{%1,%2};" : "=l"(r) : "f"(lo), "f"(hi)); return r;
}
__device__ __forceinline__ void upk2(u64 v, float& lo, float& hi) {
    asm("mov.b64 {%0,%1},%2;" : "=f"(lo), "=f"(hi) : "l"(v));
}
__device__ __forceinline__ u64 fma2(u64 a, u64 b, u64 c) {
    u64 r; asm("fma.rn.f32x2 %0,%1,%2,%3;" : "=l"(r) : "l"(a), "l"(b), "l"(c)); return r;
}
__device__ __forceinline__ u64 mul2f(u64 a, u64 b) {
    u64 r; asm("mul.rn.f32x2 %0,%1,%2;" : "=l"(r) : "l"(a), "l"(b)); return r;
}
__device__ __forceinline__ u64 add2f(u64 a, u64 b) {
    u64 r; asm("add.rn.f32x2 %0,%1,%2;" : "=l"(r) : "l"(a), "l"(b)); return r;
}

// ---------------------------------------------------------------------------
// Block = (batch b, 16-row chunk). Warp w: row group (w>>2)*8 .. +8,
// column block (w&3)*128. Lane owns 4 consecutive columns j0 = colblk + 4*lane.
//   Stage 1: s[b] -> smem TRANSPOSED s_smT[i][n] (pad 520), coalesced reads;
//            M = Q K^T in-block.
//   Stage 2: t = s.M for the 16 rows (threads 0..159).
//   Stage 3: lane loads its 4-column s slice as 10 aligned LDS.128 ->
//            sA/sB u64 pairs (zero repack). Sweep 8 rows in two 4-row
//            batches: prefetch 4 LDG.128 of G (MLP>=4), then per row:
//            10 t-broadcast LDS + 20 fma2 + square + G-mul; v kept in
//            acc registers; scalar 5-shuffle row sum.
//   Stage 4: combine 4 column-block partials in smem, inv, STG.128 epilogue.
// ---------------------------------------------------------------------------
__global__ __launch_bounds__(THREADS, 2) void attn_main(
    const float* __restrict__ s,
    const float* __restrict__ Gmat,
    const float* __restrict__ Qw,
    const float* __restrict__ Kw,
    float* __restrict__ out) {
    __shared__ float s_smT[INF * TP];     // s[b] transposed, 20.8 KB
    __shared__ float Msh[INF * INF];
    __shared__ float t_sm[R][INF];
    __shared__ float psum[R][4];
    __shared__ float inv_sm[R];

    const int tid = threadIdx.x;
    const int b = blockIdx.x / CHUNKS;
    const int row0 = (blockIdx.x % CHUNKS) * R;

    // ---- Stage 1: coalesced read of s[b], transposed store (4-way STS ok)
    {
        const float* sb = s + (size_t)b * NN * INF;
#pragma unroll
        for (int k = 0; k < (NN * INF) / THREADS; k++) {
            const int idx = tid + k * THREADS;
            const int n = idx / INF, i = idx % INF;
            s_smT[i * TP + n] = sb[idx];
        }
    }
    if (tid < INF * INF) {
        const int a = tid / INF, p = tid % INF;
        float acc = 0.0f;
#pragma unroll
        for (int m = 0; m < HIDF; m++)
            acc = fmaf(Qw[a * HIDF + m], Kw[p * HIDF + m], acc);
        Msh[tid] = acc;
    }
    __syncthreads();

    // ---- Stage 2: t[r][o] = s[row0+r] . M[:,o]  (160 threads)
    if (tid < R * INF) {
        const int r = tid / INF, o = tid % INF;
        const int n = row0 + r;
        float acc = 0.0f;
#pragma unroll
        for (int l = 0; l < INF; l++)
            acc = fmaf(s_smT[l * TP + n], Msh[l * INF + o], acc);
        t_sm[r][o] = acc;
    }
    __syncthreads();

    // ---- warp decomposition
    const int w = tid >> 5, lane = tid & 31;
    const int r0 = (w >> 2) * 8;             // 8 rows for this warp group
    const int j0 = ((w & 3) << 7) + (lane << 2);  // 4 consecutive columns

    // ---- lane-private s slice: 10 aligned LDS.128, pairs fall out directly
    u64 sA[INF], sB[INF];
#pragma unroll
    for (int i = 0; i < INF; i++) {
        const float4 q = *(const float4*)(s_smT + i * TP + j0);
        sA[i] = pk2(q.x, q.y);
        sB[i] = pk2(q.z, q.w);
    }

    const char* gbase = (const char*)(Gmat + ((size_t)b * NN + row0 + r0) * NN + j0);
    u64 accA[8], accB[8];

    // ---- Stage 3: two 4-row batches with explicit G prefetch (MLP >= 4)
#pragma unroll
    for (int rb = 0; rb < 8; rb += 4) {
        ulonglong2 g4[4];
#pragma unroll
        for (int k = 0; k < 4; k++)
            g4[k] = *(const ulonglong2*)(gbase + (size_t)(rb + k) * (NN * 4));

#pragma unroll
        for (int k = 0; k < 4; k++) {
            const int r = rb + k;
            u64 d0 = pk2(0.0f, 0.0f);
            u64 d1 = pk2(0.0f, 0.0f);
#pragma unroll
            for (int i = 0; i < INF; i++) {
                const float tv = t_sm[r0 + r][i];   // uniform broadcast
                const u64 tsp = pk2(tv, tv);
                d0 = fma2(sA[i], tsp, d0);
                d1 = fma2(sB[i], tsp, d1);
            }
            const u64 vA = mul2f(mul2f(d0, d0), g4[k].x);
            const u64 vB = mul2f(mul2f(d1, d1), g4[k].y);
            accA[r] = vA;
            accB[r] = vB;

            float a0, a1, b0, b1;
            upk2(vA, a0, a1);
            upk2(vB, b0, b1);
            float sv = (a0 + a1) + (b0 + b1);       // lane's 4-col partial
#pragma unroll
            for (int off = 16; off > 0; off >>= 1)
                sv += __shfl_xor_sync(0xffffffffu, sv, off);
            if (lane == 0) psum[r0 + r][w & 3] = sv;
        }
    }
    __syncthreads();

    // ---- Stage 4: combine 4 column-block partials, inv
    if (tid < R)
        inv_sm[tid] = 1.0f / (psum[tid][0] + psum[tid][1] +
                              psum[tid][2] + psum[tid][3] + 0.001f);
    __syncthreads();

    // ---- normalized STG.128 epilogue
    char* obase = (char*)(out + ((size_t)b * NN + row0 + r0) * NN + j0);
#pragma unroll
    for (int r = 0; r < 8; r++) {
        const float iv = inv_sm[r0 + r];
        const u64 ivp = pk2(iv, iv);
        ulonglong2 o2;
        o2.x = mul2f(accA[r], ivp);
        o2.y = mul2f(accB[r], ivp);
        *(ulonglong2*)(obase + (size_t)r * (NN * 4)) = o2;
    }
}

// ---------------------------------------------------------------------------
extern "C" void kernel_launch(void* const* d_in, const int* in_sizes, int n_in,
                              void* d_out, int out_size) {
    const float* s    = (const float*)d_in[0];
    const float* Gmat = (const float*)d_in[1];
    const float* Qw   = (const float*)d_in[2];
    const float* Kw   = (const float*)d_in[3];
    float* out = (float*)d_out;

    attn_main<<<BB * CHUNKS, THREADS>>>(s, Gmat, Qw, Kw, out);
}

// round 13
// speedup vs baseline: 1.1514x; 1.1514x over previous
#include <cuda_runtime.h>

#define BB 256
#define NN 512
#define INF 10
#define HIDF 32
#define R 16                      // rows per block
#define WARPS 8
#define THREADS (WARPS * 32)
#define CHUNKS (NN / R)           // 32
#define TP 520                    // transposed s row length (512 + 8 pad)

typedef unsigned long long u64;

// ---- packed f32x2 helpers (sm_103a FFMA2 path, PTX-only) -------------------
__device__ __forceinline__ u64 pk2(float lo, float hi) {
    u64 r; asm("mov.b64 %0,{%1,%2};" : "=l"(r) : "f"(lo), "f"(hi)); return r;
}
__device__ __forceinline__ void upk2(u64 v, float& lo, float& hi) {
    asm("mov.b64 {%0,%1},%2;" : "=f"(lo), "=f"(hi) : "l"(v));
}
__device__ __forceinline__ u64 fma2(u64 a, u64 b, u64 c) {
    u64 r; asm("fma.rn.f32x2 %0,%1,%2,%3;" : "=l"(r) : "l"(a), "l"(b), "l"(c)); return r;
}
__device__ __forceinline__ u64 mul2f(u64 a, u64 b) {
    u64 r; asm("mul.rn.f32x2 %0,%1,%2;" : "=l"(r) : "l"(a), "l"(b)); return r;
}
__device__ __forceinline__ u64 add2f(u64 a, u64 b) {
    u64 r; asm("add.rn.f32x2 %0,%1,%2;" : "=l"(r) : "l"(a), "l"(b)); return r;
}

// ---------------------------------------------------------------------------
// Block = (batch b, 16-row chunk). Warp w: rows (w>>2)*8..+8, column block
// (w&3)*128; lane owns 4 consecutive columns.
//   Stage 1: s[b] -> smem transposed (pad 520), coalesced reads; M in-block.
//   Stage 2: t = s.M for the 16 rows.
//   Stage 3: lane's s-slice via 10 LDS.128 -> sA/sB registers.
//            ALL 8 G rows prefetched (LDG.128, MLP=8). Row loop is pure
//            compute: t-broadcast, 4 split fma2 chains, square, G-mul;
//            scalar row-partials kept in registers — NO shuffles in loop.
//   Stage 4: 4 independent packed bfly reductions (pipelined), smem combine
//            across the 4 column blocks, inv, STG.128 epilogue.
// ---------------------------------------------------------------------------
__global__ __launch_bounds__(THREADS, 2) void attn_main(
    const float* __restrict__ s,
    const float* __restrict__ Gmat,
    const float* __restrict__ Qw,
    const float* __restrict__ Kw,
    float* __restrict__ out) {
    __shared__ float s_smT[INF * TP];     // s[b] transposed, 20.8 KB
    __shared__ float Msh[INF * INF];
    __shared__ float t_sm[R][INF];
    __shared__ float psum[R][4];
    __shared__ float inv_sm[R];

    const int tid = threadIdx.x;
    const int b = blockIdx.x / CHUNKS;
    const int row0 = (blockIdx.x % CHUNKS) * R;

    // ---- Stage 1: coalesced read of s[b], transposed store; M in-block
    {
        const float* sb = s + (size_t)b * NN * INF;
#pragma unroll
        for (int k = 0; k < (NN * INF) / THREADS; k++) {
            const int idx = tid + k * THREADS;
            s_smT[(idx % INF) * TP + (idx / INF)] = sb[idx];
        }
    }
    if (tid < INF * INF) {
        const int a = tid / INF, p = tid % INF;
        float acc = 0.0f;
#pragma unroll
        for (int m = 0; m < HIDF; m++)
            acc = fmaf(Qw[a * HIDF + m], Kw[p * HIDF + m], acc);
        Msh[tid] = acc;
    }
    __syncthreads();

    // ---- Stage 2: t[r][o] = s[row0+r] . M[:,o]  (160 threads)
    if (tid < R * INF) {
        const int r = tid / INF, o = tid % INF;
        const int n = row0 + r;
        float acc = 0.0f;
#pragma unroll
        for (int l = 0; l < INF; l++)
            acc = fmaf(s_smT[l * TP + n], Msh[l * INF + o], acc);
        t_sm[r][o] = acc;
    }
    __syncthreads();

    // ---- warp decomposition
    const int w = tid >> 5, lane = tid & 31;
    const int r0 = (w >> 2) * 8;
    const int cb = w & 3;
    const int j0 = (cb << 7) + (lane << 2);

    // ---- lane-private s slice (10 aligned LDS.128)
    u64 sA[INF], sB[INF];
#pragma unroll
    for (int i = 0; i < INF; i++) {
        const float4 q = *(const float4*)(s_smT + i * TP + j0);
        sA[i] = pk2(q.x, q.y);
        sB[i] = pk2(q.z, q.w);
    }

    // ---- prefetch ALL 8 G rows (back-to-back LDG.128, MLP = 8)
    const char* gbase = (const char*)(Gmat + ((size_t)b * NN + row0 + r0) * NN + j0);
    ulonglong2 g8[8];
#pragma unroll
    for (int r = 0; r < 8; r++)
        g8[r] = *(const ulonglong2*)(gbase + (size_t)r * (NN * 4));

    // ---- Stage 3: pure-compute row loop, reductions deferred
    u64 accA[8], accB[8];
    float part[8];
#pragma unroll
    for (int r = 0; r < 8; r++) {
        u64 d0a = pk2(0.0f, 0.0f), d0b = pk2(0.0f, 0.0f);
        u64 d1a = pk2(0.0f, 0.0f), d1b = pk2(0.0f, 0.0f);
#pragma unroll
        for (int i = 0; i < INF; i += 2) {
            const float tv0 = t_sm[r0 + r][i];
            const float tv1 = t_sm[r0 + r][i + 1];
            const u64 tp0 = pk2(tv0, tv0);
            const u64 tp1 = pk2(tv1, tv1);
            d0a = fma2(sA[i],     tp0, d0a);
            d1a = fma2(sB[i],     tp0, d1a);
            d0b = fma2(sA[i + 1], tp1, d0b);
            d1b = fma2(sB[i + 1], tp1, d1b);
        }
        const u64 d0 = add2f(d0a, d0b);
        const u64 d1 = add2f(d1a, d1b);
        const u64 vA = mul2f(mul2f(d0, d0), g8[r].x);
        const u64 vB = mul2f(mul2f(d1, d1), g8[r].y);
        accA[r] = vA;
        accB[r] = vB;
        float x, y;
        upk2(add2f(vA, vB), x, y);
        part[r] = x + y;                      // lane's 4-col partial, in regs
    }

    // ---- Stage 4a: 4 independent packed bfly chains (interleaved by ptxas)
    u64 p01 = pk2(part[0], part[1]);
    u64 p23 = pk2(part[2], part[3]);
    u64 p45 = pk2(part[4], part[5]);
    u64 p67 = pk2(part[6], part[7]);
#pragma unroll
    for (int off = 16; off > 0; off >>= 1) {
        p01 = add2f(p01, __shfl_xor_sync(0xffffffffu, p01, off));
        p23 = add2f(p23, __shfl_xor_sync(0xffffffffu, p23, off));
        p45 = add2f(p45, __shfl_xor_sync(0xffffffffu, p45, off));
        p67 = add2f(p67, __shfl_xor_sync(0xffffffffu, p67, off));
    }
    if (lane == 0) {
        float x, y;
        upk2(p01, x, y); psum[r0 + 0][cb] = x; psum[r0 + 1][cb] = y;
        upk2(p23, x, y); psum[r0 + 2][cb] = x; psum[r0 + 3][cb] = y;
        upk2(p45, x, y); psum[r0 + 4][cb] = x; psum[r0 + 5][cb] = y;
        upk2(p67, x, y); psum[r0 + 6][cb] = x; psum[r0 + 7][cb] = y;
    }
    __syncthreads();
    if (tid < R)
        inv_sm[tid] = 1.0f / (psum[tid][0] + psum[tid][1] +
                              psum[tid][2] + psum[tid][3] + 0.001f);
    __syncthreads();

    // ---- Stage 4b: normalized STG.128 epilogue
    char* obase = (char*)(out + ((size_t)b * NN + row0 + r0) * NN + j0);
#pragma unroll
    for (int r = 0; r < 8; r++) {
        const float iv = inv_sm[r0 + r];
        const u64 ivp = pk2(iv, iv);
        ulonglong2 o2;
        o2.x = mul2f(accA[r], ivp);
        o2.y = mul2f(accB[r], ivp);
        *(ulonglong2*)(obase + (size_t)r * (NN * 4)) = o2;
    }
}

// ---------------------------------------------------------------------------
extern "C" void kernel_launch(void* const* d_in, const int* in_sizes, int n_in,
                              void* d_out, int out_size) {
    const float* s    = (const float*)d_in[0];
    const float* Gmat = (const float*)d_in[1];
    const float* Qw   = (const float*)d_in[2];
    const float* Kw   = (const float*)d_in[3];
    float* out = (float*)d_out;

    attn_main<<<BB * CHUNKS, THREADS>>>(s, Gmat, Qw, Kw, out);
}

// round 15
// speedup vs baseline: 1.7073x; 1.4829x over previous
#include <cuda_runtime.h>

#define BB 256
#define NN 512
#define INF 10
#define HIDF 32
#define R 128                     // rows per block
#define WARPS 8
#define THREADS (WARPS * 32)
#define CHUNKS (NN / R)           // 4
#define TP 520                    // transposed s row stride (pad)

typedef unsigned long long u64;

// ---- packed f32x2 helpers (sm_103a FFMA2 path, PTX-only) -------------------
__device__ __forceinline__ u64 pk2(float lo, float hi) {
    u64 r; asm("mov.b64 %0,{%1,%2};" : "=l"(r) : "f"(lo), "f"(hi)); return r;
}
__device__ __forceinline__ void upk2(u64 v, float& lo, float& hi) {
    asm("mov.b64 {%0,%1},%2;" : "=f"(lo), "=f"(hi) : "l"(v));
}
__device__ __forceinline__ u64 fma2(u64 a, u64 b, u64 c) {
    u64 r; asm("fma.rn.f32x2 %0,%1,%2,%3;" : "=l"(r) : "l"(a), "l"(b), "l"(c)); return r;
}
__device__ __forceinline__ u64 mul2f(u64 a, u64 b) {
    u64 r; asm("mul.rn.f32x2 %0,%1,%2;" : "=l"(r) : "l"(a), "l"(b)); return r;
}
__device__ __forceinline__ u64 add2f(u64 a, u64 b) {
    u64 r; asm("add.rn.f32x2 %0,%1,%2;" : "=l"(r) : "l"(a), "l"(b)); return r;
}

// ---------------------------------------------------------------------------
// R4's proven inner loop, amortized over 128-row persistent-ish blocks.
// Block = (batch b, 128-row quarter). Warp sweeps 8 row-PAIRS (p = w + 8k);
// per pair: 16-u sweep over all 512 cols, s broadcast-splat shared by the
// pair, acc[16] in registers, packed 5-shuffle row-sum, single-pass
// normalized stores. No cross-warp coupling in the main loop.
// ---------------------------------------------------------------------------
__global__ __launch_bounds__(THREADS, 2) void attn_main(
    const float* __restrict__ s,
    const float* __restrict__ Gmat,
    const float* __restrict__ Qw,
    const float* __restrict__ Kw,
    float* __restrict__ out) {
    __shared__ float s_smT[INF * TP];    // s[b] transposed (20.8 KB)
    __shared__ float Msh[INF * INF];
    __shared__ float t_sm[R][INF];       // t for this block's 128 rows (5 KB)

    const int tid = threadIdx.x;
    const int b = blockIdx.x / CHUNKS;
    const int row0 = (blockIdx.x % CHUNKS) * R;

    // ---- Stage 1: s[b] -> smem transposed; M in-block
    {
        const float* sb = s + (size_t)b * NN * INF;
        for (int n = tid; n < NN; n += THREADS) {
#pragma unroll
            for (int i = 0; i < INF; i++)
                s_smT[i * TP + n] = sb[n * INF + i];   // contiguous read, clean STS
        }
    }
    if (tid < INF * INF) {
        const int a = tid / INF, p = tid % INF;
        float acc = 0.0f;
#pragma unroll
        for (int m = 0; m < HIDF; m++)
            acc = fmaf(Qw[a * HIDF + m], Kw[p * HIDF + m], acc);
        Msh[tid] = acc;
    }
    __syncthreads();

    // ---- Stage 2: t for 128 rows, all 256 threads (5 values each)
#pragma unroll
    for (int k = 0; k < (R * INF) / THREADS; k++) {
        const int idx = tid + k * THREADS;
        const int r = idx / INF, o = idx % INF;
        const int n = row0 + r;
        float acc = 0.0f;
#pragma unroll
        for (int l = 0; l < INF; l++)
            acc = fmaf(s_smT[l * TP + n], Msh[l * INF + o], acc);
        t_sm[r][o] = acc;
    }
    __syncthreads();

    // ---- Stage 3: R4 main loop over 8 row-pairs per warp
    const int w = tid >> 5, lane = tid & 31;

#pragma unroll
    for (int k = 0; k < 8; k++) {
        const int p = w + k * WARPS;          // pair index 0..63
        const int r0 = 2 * p;                 // rows r0, r0+1 of the chunk
        const int n0 = row0 + r0;

        u64 tp[INF];
#pragma unroll
        for (int i = 0; i < INF; i++)
            tp[i] = pk2(t_sm[r0][i], t_sm[r0 + 1][i]);

        const float* g0 = Gmat + ((size_t)b * NN + n0) * NN;
        const float* g1 = g0 + NN;
        float* o0 = out + ((size_t)b * NN + n0) * NN;
        float* o1 = o0 + NN;

        u64 acc[16];
        u64 sum2 = pk2(0.0f, 0.0f);
#pragma unroll
        for (int u = 0; u < 16; u++) {
            const int j = lane + (u << 5);
            u64 d = pk2(0.0f, 0.0f);
#pragma unroll
            for (int i = 0; i < INF; i++) {
                const float sj = s_smT[i * TP + j];   // conflict-free LDS
                d = fma2(tp[i], pk2(sj, sj), d);
            }
            const u64 g = pk2(g0[j], g1[j]);
            const u64 v = mul2f(mul2f(d, d), g);
            acc[u] = v;
            sum2 = add2f(sum2, v);
        }

        // packed warp reduction of both row sums
#pragma unroll
        for (int off = 16; off > 0; off >>= 1)
            sum2 = add2f(sum2, __shfl_xor_sync(0xffffffffu, sum2, off));

        float sa, sb2;
        upk2(sum2, sa, sb2);
        const float inv0 = 1.0f / (sa + 0.001f);
        const float inv1 = 1.0f / (sb2 + 0.001f);

#pragma unroll
        for (int u = 0; u < 16; u++) {
            const int j = lane + (u << 5);
            float a, bv;
            upk2(acc[u], a, bv);
            o0[j] = a * inv0;
            o1[j] = bv * inv1;
        }
    }
}

// ---------------------------------------------------------------------------
extern "C" void kernel_launch(void* const* d_in, const int* in_sizes, int n_in,
                              void* d_out, int out_size) {
    const float* s    = (const float*)d_in[0];
    const float* Gmat = (const float*)d_in[1];
    const float* Qw   = (const float*)d_in[2];
    const float* Kw   = (const float*)d_in[3];
    float* out = (float*)d_out;

    attn_main<<<BB * CHUNKS, THREADS>>>(s, Gmat, Qw, Kw, out);
}